// round 7
// baseline (speedup 1.0000x reference)
#include <cuda_runtime.h>
#include <math.h>

#define H 1024
#define V 50257
#define L 512
#define GRID 148
#define TPB 512
#define NW 16                 // warps per block
#define ROWS_PB 340           // ceil(V / GRID)

// ---------------- scratch (device globals; no allocations allowed) ----------
__device__ float g_qpart[2048];          // attn score quarter-partials
__device__ float g_attn_partial[8][H];
__device__ float g_gru_in[H];
__device__ float g_gates[6 * H];         // [0,3H)=gx, [3H,6H)=gh
__device__ float g_logits[V];
__device__ float g_pm[GRID], g_ps[GRID];
__device__ unsigned g_bars[8];

__global__ void k_reset() {
    if (threadIdx.x < 8) g_bars[threadIdx.x] = 0u;
}

__device__ __forceinline__ float4 ldg4(const float4* p) {
    float4 v;
    asm volatile("ld.global.nc.v4.f32 {%0,%1,%2,%3},[%4];"
                 : "=f"(v.x), "=f"(v.y), "=f"(v.z), "=f"(v.w) : "l"(p));
    return v;
}
__device__ __forceinline__ float ldg1(const float* p) {
    float v;
    asm volatile("ld.global.nc.f32 %0,[%1];" : "=f"(v) : "l"(p));
    return v;
}
__device__ __forceinline__ float wsum(float v) {
#pragma unroll
    for (int o = 16; o; o >>= 1) v += __shfl_down_sync(0xffffffffu, v, o);
    return v;
}

// software grid barrier: 148 CTAs, 1/SM, all resident in wave 1 -> spin safe.
// nanosleep backoff keeps L2 pressure low and plays nice with profiling replay.
__device__ __forceinline__ void gbar(int ph) {
    __syncthreads();
    if (threadIdx.x == 0) {
        __threadfence();
        unsigned arrived = atomicAdd(&g_bars[ph], 1u) + 1u;
        if (arrived < GRID) {
            volatile unsigned* p = &g_bars[ph];
            while (*p < GRID) { __nanosleep(64); }
        }
        __threadfence();
    }
    __syncthreads();
}

__global__ void __launch_bounds__(TPB, 1)
k_fused(const int* __restrict__ x,
        const float* __restrict__ enc,
        const float* __restrict__ hidden,
        const float* __restrict__ emb,
        const float* __restrict__ attn_W,
        const float* __restrict__ attn_b,
        const float* __restrict__ comb_W,
        const float* __restrict__ comb_b,
        const float* __restrict__ W_ih,
        const float* __restrict__ W_hh,
        const float* __restrict__ b_ih,
        const float* __restrict__ b_hh,
        const float* __restrict__ out_W,
        const float* __restrict__ out_b,
        float* __restrict__ out) {
    __shared__ float s_emb[H];
    __shared__ float s_h0[H];
    __shared__ float s_vec[H];
    __shared__ float s_attnw[L];
    __shared__ float red[512], red2[512];
    __shared__ float wm[NW], wsm[NW];

    const int t = threadIdx.x, b = blockIdx.x;
    const int wid = t >> 5, lane = t & 31;

    // preload emb row + hidden into shared
    {
        const float* er = emb + (size_t)x[0] * H;
        for (int i = t; i < H; i += TPB) { s_emb[i] = ldg1(er + i); s_h0[i] = ldg1(hidden + i); }
        __syncthreads();
    }

    // ---- Phase A: attn-score quarter partials (2048 jobs, 512 cols each)
    //      + W_hh gate GEMV (3072 jobs, 1024 cols) — both depend only on inputs
    for (int job = b * NW + wid; job < 5120; job += GRID * NW) {
        if (job < 2048) {
            const int row = job >> 2, q = job & 3;
            const float* vp = (q < 2) ? (s_emb + q * 512) : (s_h0 + (q - 2) * 512);
            const float4* Wr = (const float4*)(attn_W + (size_t)row * (2 * H) + q * 512);
            const float4* sv = (const float4*)vp;
            float4 w[4];
#pragma unroll
            for (int i = 0; i < 4; i++) w[i] = ldg4(Wr + lane + i * 32);
            float acc = 0.f;
#pragma unroll
            for (int i = 0; i < 4; i++) {
                float4 v = sv[lane + i * 32];
                acc += w[i].x * v.x + w[i].y * v.y + w[i].z * v.z + w[i].w * v.w;
            }
            acc = wsum(acc);
            if (lane == 0) g_qpart[job] = acc;
        } else {
            const int r = job - 2048;
            const float4* Wr = (const float4*)(W_hh + (size_t)r * H);
            const float4* sv = (const float4*)s_h0;
            float4 w[8];
#pragma unroll
            for (int i = 0; i < 8; i++) w[i] = ldg4(Wr + lane + i * 32);
            float acc = 0.f;
#pragma unroll
            for (int i = 0; i < 8; i++) {
                float4 v = sv[lane + i * 32];
                acc += w[i].x * v.x + w[i].y * v.y + w[i].z * v.z + w[i].w * v.w;
            }
            acc = wsum(acc);
            if (lane == 0) g_gates[3 * H + r] = acc + ldg1(b_hh + r);
        }
    }
    gbar(0);

    // ---- Phase B: blocks 0..63: redundant softmax (L=512) then attn apply --
    if (b < 64) {
        const float sc = g_qpart[4 * t] + g_qpart[4 * t + 1] + g_qpart[4 * t + 2]
                       + g_qpart[4 * t + 3] + ldg1(attn_b + t);
        red[t] = sc;
        __syncthreads();
        for (int o = 256; o; o >>= 1) {
            if (t < o) red[t] = fmaxf(red[t], red[t + o]);
            __syncthreads();
        }
        const float m = red[0];
        __syncthreads();
        const float e = expf(sc - m);
        red[t] = e;
        __syncthreads();
        for (int o = 256; o; o >>= 1) {
            if (t < o) red[t] += red[t + o];
            __syncthreads();
        }
        const float aw = e / red[0];
        s_attnw[t] = aw;
        if (b == 0) out[V + t] = aw;
        __syncthreads();

        // attn apply: this block covers (lc = b>>3) 64-L-chunk, (jc = b&7) 128-col chunk
        const int lc = b >> 3, jc = b & 7;
        const int j = jc * 128 + (t & 127);
        const int sub = t >> 7;                 // 0..3, 16 L-rows each
        const int l0 = lc * 64 + sub * 16;
        float ev[16];
#pragma unroll
        for (int u = 0; u < 16; u++) ev[u] = ldg1(enc + (size_t)(l0 + u) * H + j);
        float acc = 0.f;
#pragma unroll
        for (int u = 0; u < 16; u++) acc += s_attnw[l0 + u] * ev[u];
        red[t] = acc;
        __syncthreads();
        if (t < 128)
            g_attn_partial[lc][jc * 128 + t] = red[t] + red[t + 128] + red[t + 256] + red[t + 384];
    }
    gbar(1);

    // ---- Phase C: blocks 0..127: combine + relu (8 rows/block, 2 warps/row)
    if (b < 128) {
        for (int i = t; i < H; i += TPB) {
            float a = 0.f;
#pragma unroll
            for (int c = 0; c < 8; c++) a += g_attn_partial[c][i];
            s_vec[i] = a;
        }
        __syncthreads();
        const int row = b * 8 + (wid >> 1), half = wid & 1;
        const float* vp = half ? s_vec : s_emb;
        const float4* Wr = (const float4*)(comb_W + (size_t)row * (2 * H) + half * H);
        const float4* sv = (const float4*)vp;
        float4 w[8];
#pragma unroll
        for (int i = 0; i < 8; i++) w[i] = ldg4(Wr + lane + i * 32);
        float acc = 0.f;
#pragma unroll
        for (int i = 0; i < 8; i++) {
            float4 v = sv[lane + i * 32];
            acc += w[i].x * v.x + w[i].y * v.y + w[i].z * v.z + w[i].w * v.w;
        }
        acc = wsum(acc);
        if (lane == 0) red[wid] = acc;
        __syncthreads();
        if (t < 8) {
            const int r = b * 8 + t;
            g_gru_in[r] = fmaxf(red[2 * t] + red[2 * t + 1] + ldg1(comb_b + r), 0.f);
        }
    }
    gbar(2);

    // ---- Phase D: W_ih gate GEMV (3072 warp-jobs over 2368 warps) ----------
    for (int i = t; i < H; i += TPB) s_vec[i] = g_gru_in[i];
    __syncthreads();
    for (int job = b * NW + wid; job < 3 * H; job += GRID * NW) {
        const float4* Wr = (const float4*)(W_ih + (size_t)job * H);
        const float4* sv = (const float4*)s_vec;
        float4 w[8];
#pragma unroll
        for (int i = 0; i < 8; i++) w[i] = ldg4(Wr + lane + i * 32);
        float acc = 0.f;
#pragma unroll
        for (int i = 0; i < 8; i++) {
            float4 v = sv[lane + i * 32];
            acc += w[i].x * v.x + w[i].y * v.y + w[i].z * v.z + w[i].w * v.w;
        }
        acc = wsum(acc);
        if (lane == 0) g_gates[job] = acc + ldg1(b_ih + job);
    }
    gbar(3);

    // ---- Phase E: redundant GRU elementwise -> s_vec = h_new ---------------
    __syncthreads();
    for (int i = t; i < H; i += TPB) {
        const float gxr = g_gates[i],         ghr = g_gates[3 * H + i];
        const float gxz = g_gates[H + i],     ghz = g_gates[4 * H + i];
        const float gxn = g_gates[2 * H + i], ghn = g_gates[5 * H + i];
        const float r = 1.f / (1.f + expf(-(gxr + ghr)));
        const float z = 1.f / (1.f + expf(-(gxz + ghz)));
        const float n = tanhf(gxn + r * ghn);
        s_vec[i] = (1.f - z) * n + z * s_h0[i];
    }
    __syncthreads();

    // ---- Phase E2: big GEMV (double-buffered prefetch, sv in registers) ----
    const int r0 = b * ROWS_PB;
    const int r1 = (r0 + ROWS_PB < V) ? (r0 + ROWS_PB) : V;
    {
        float4 sv[8];
#pragma unroll
        for (int i = 0; i < 8; i++) sv[i] = ((const float4*)s_vec)[lane + i * 32];

        float m = -INFINITY, ssum = 0.f;
        float4 wb[2][8];
        float bias[2];
        int r = r0 + wid;
        if (r < r1) {
            const float4* Wr = (const float4*)(out_W + (size_t)r * H);
#pragma unroll
            for (int i = 0; i < 8; i++) wb[0][i] = ldg4(Wr + lane + i * 32);
            bias[0] = ldg1(out_b + r);
        }
        int cur = 0;
        for (; r < r1; r += NW, cur ^= 1) {
            const int rn = r + NW;
            if (rn < r1) {
                const float4* Wn = (const float4*)(out_W + (size_t)rn * H);
#pragma unroll
                for (int i = 0; i < 8; i++) wb[cur ^ 1][i] = ldg4(Wn + lane + i * 32);
                bias[cur ^ 1] = ldg1(out_b + rn);
            }
            float acc = 0.f;
#pragma unroll
            for (int i = 0; i < 8; i++) {
                acc += wb[cur][i].x * sv[i].x + wb[cur][i].y * sv[i].y
                     + wb[cur][i].z * sv[i].z + wb[cur][i].w * sv[i].w;
            }
            acc = wsum(acc);
            if (lane == 0) {
                const float lg = acc + bias[cur];
                g_logits[r] = lg;
                const float nm = fmaxf(m, lg);
                ssum = ssum * expf(m - nm) + expf(lg - nm);
                m = nm;
            }
        }
        if (lane == 0) { wm[wid] = m; wsm[wid] = ssum; }
        __syncthreads();
        for (int o = 8; o; o >>= 1) {
            if (t < o) {
                const float m2 = wm[t + o], s2 = wsm[t + o];
                const float nm = fmaxf(wm[t], m2);
                wsm[t] = wsm[t] * expf(wm[t] - nm) + s2 * expf(m2 - nm);
                wm[t] = nm;
            }
            __syncthreads();
        }
        if (t == 0) { g_pm[b] = wm[0]; g_ps[b] = wsm[0]; }
    }
    gbar(4);

    // ---- Phase F: redundant partial combine (identical tree), write logp ---
    {
        if (t < 256) {
            red[t]  = (t < GRID) ? g_pm[t] : -INFINITY;
            red2[t] = (t < GRID) ? g_ps[t] : 0.f;
        }
        __syncthreads();
        for (int o = 128; o; o >>= 1) {
            if (t < o) {
                const float m2 = red[t + o], s2 = red2[t + o];
                const float nm = fmaxf(red[t], m2);
                red2[t] = red2[t] * expf(red[t] - nm) + s2 * expf(m2 - nm);
                red[t] = nm;
            }
            __syncthreads();
        }
        const float lse = red[0] + logf(red2[0]);
        for (int v = r0 + t; v < r1; v += TPB) out[v] = g_logits[v] - lse;
    }
}

extern "C" void kernel_launch(void* const* d_in, const int* in_sizes, int n_in,
                              void* d_out, int out_size) {
    const int*   x      = (const int*)  d_in[0];
    const float* enc    = (const float*)d_in[1];
    const float* hidden = (const float*)d_in[2];
    const float* emb    = (const float*)d_in[3];
    const float* attn_W = (const float*)d_in[4];
    const float* attn_b = (const float*)d_in[5];
    const float* comb_W = (const float*)d_in[6];
    const float* comb_b = (const float*)d_in[7];
    const float* W_ih   = (const float*)d_in[8];
    const float* W_hh   = (const float*)d_in[9];
    const float* b_ih   = (const float*)d_in[10];
    const float* b_hh   = (const float*)d_in[11];
    const float* out_W  = (const float*)d_in[12];
    const float* out_b  = (const float*)d_in[13];
    float* out = (float*)d_out;   // [0,V): logp ; [V,V+L): attn_weights

    k_reset<<<1, 32>>>();
    k_fused<<<GRID, TPB>>>(x, enc, hidden, emb, attn_W, attn_b, comb_W, comb_b,
                           W_ih, W_hh, b_ih, b_hh, out_W, out_b, out);
}

// round 8
// speedup vs baseline: 1.1872x; 1.1872x over previous
#include <cuda_runtime.h>
#include <math.h>

#define H 1024
#define V 50257
#define L 512
#define GRID 148
#define TPB 1024
#define NW 32                 // warps per block
#define ROWS_PB 340           // ceil(V / GRID)

// ---------------- scratch (device globals; no allocations allowed) ----------
__device__ float g_qpart[2048];          // attn score quarter-partials
__device__ float g_attn_partial[8][H];
__device__ float g_gru_in[H];
__device__ float g_gates[6 * H];         // [0,3H)=gx, [3H,6H)=gh
__device__ float g_logits[V];
__device__ unsigned g_bars[8];

__global__ void k_reset() {
    if (threadIdx.x < 8) g_bars[threadIdx.x] = 0u;
}

__device__ __forceinline__ float4 ldg4(const float4* p) {
    float4 v;
    asm volatile("ld.global.nc.v4.f32 {%0,%1,%2,%3},[%4];"
                 : "=f"(v.x), "=f"(v.y), "=f"(v.z), "=f"(v.w) : "l"(p));
    return v;
}
__device__ __forceinline__ float ldg1(const float* p) {
    float v;
    asm volatile("ld.global.nc.f32 %0,[%1];" : "=f"(v) : "l"(p));
    return v;
}
__device__ __forceinline__ float wsum(float v) {
#pragma unroll
    for (int o = 16; o; o >>= 1) v += __shfl_down_sync(0xffffffffu, v, o);
    return v;
}

// grid barrier: 148 CTAs, 1/SM, all resident in wave 1 -> spin safe.
__device__ __forceinline__ void gbar(int ph) {
    __syncthreads();
    if (threadIdx.x == 0) {
        __threadfence();
        unsigned arrived = atomicAdd(&g_bars[ph], 1u) + 1u;
        if (arrived < GRID) {
            volatile unsigned* p = &g_bars[ph];
            while (*p < GRID) { __nanosleep(64); }
        }
        __threadfence();
    }
    __syncthreads();
}

__global__ void __launch_bounds__(TPB, 1)
k_fused(const int* __restrict__ x,
        const float* __restrict__ enc,
        const float* __restrict__ hidden,
        const float* __restrict__ emb,
        const float* __restrict__ attn_W,
        const float* __restrict__ attn_b,
        const float* __restrict__ comb_W,
        const float* __restrict__ comb_b,
        const float* __restrict__ W_ih,
        const float* __restrict__ W_hh,
        const float* __restrict__ b_ih,
        const float* __restrict__ b_hh,
        const float* __restrict__ out_W,
        const float* __restrict__ out_b,
        float* __restrict__ out) {
    __shared__ float s_emb[H];
    __shared__ float s_h0[H];
    __shared__ float s_vec[H];
    __shared__ float s_attnw[L];
    __shared__ float red[1024], red2[1024];

    const int t = threadIdx.x, b = blockIdx.x;
    const int wid = t >> 5, lane = t & 31;

    // preload emb row + hidden into shared
    {
        const float* er = emb + (size_t)x[0] * H;
        s_emb[t] = ldg1(er + t);
        s_h0[t] = ldg1(hidden + t);
        __syncthreads();
    }

    // ---- Phase A: attn-score quarter partials (2048 jobs, 512 cols)
    //      + W_hh gate GEMV (3072 jobs, 1024 cols) — depend only on inputs ---
    for (int job = b * NW + wid; job < 5120; job += GRID * NW) {
        if (job < 2048) {
            const int row = job >> 2, q = job & 3;
            const float* vp = (q < 2) ? (s_emb + q * 512) : (s_h0 + (q - 2) * 512);
            const float4* Wr = (const float4*)(attn_W + (size_t)row * (2 * H) + q * 512);
            const float4* sv = (const float4*)vp;
            float4 w[4];
#pragma unroll
            for (int i = 0; i < 4; i++) w[i] = ldg4(Wr + lane + i * 32);
            float acc = 0.f;
#pragma unroll
            for (int i = 0; i < 4; i++) {
                float4 v = sv[lane + i * 32];
                acc += w[i].x * v.x + w[i].y * v.y + w[i].z * v.z + w[i].w * v.w;
            }
            acc = wsum(acc);
            if (lane == 0) g_qpart[job] = acc;
        } else {
            const int r = job - 2048;
            const float4* Wr = (const float4*)(W_hh + (size_t)r * H);
            const float4* sv = (const float4*)s_h0;
            float4 w[8];
#pragma unroll
            for (int i = 0; i < 8; i++) w[i] = ldg4(Wr + lane + i * 32);
            float acc = 0.f;
#pragma unroll
            for (int i = 0; i < 8; i++) {
                float4 v = sv[lane + i * 32];
                acc += w[i].x * v.x + w[i].y * v.y + w[i].z * v.z + w[i].w * v.w;
            }
            acc = wsum(acc);
            if (lane == 0) g_gates[3 * H + r] = acc + ldg1(b_hh + r);
        }
    }
    gbar(0);

    // ---- Phase B: blocks 0..63: redundant softmax (L=512), then attn apply -
    if (b < 64) {
        float sc = -INFINITY;
        if (t < L)
            sc = g_qpart[4 * t] + g_qpart[4 * t + 1] + g_qpart[4 * t + 2]
               + g_qpart[4 * t + 3] + ldg1(attn_b + t);
        red[t] = sc;
        __syncthreads();
        for (int o = 512; o; o >>= 1) {
            if (t < o) red[t] = fmaxf(red[t], red[t + o]);
            __syncthreads();
        }
        const float m = red[0];
        __syncthreads();
        const float e = (t < L) ? expf(sc - m) : 0.f;
        red[t] = e;
        __syncthreads();
        for (int o = 512; o; o >>= 1) {
            if (t < o) red[t] += red[t + o];
            __syncthreads();
        }
        if (t < L) {
            const float aw = e / red[0];
            s_attnw[t] = aw;
            if (b == 0) out[V + t] = aw;
        }
        __syncthreads();

        // attn apply: block covers (lc = b>>3) 64-L-chunk, (jc = b&7) 128 cols
        const int lc = b >> 3, jc = b & 7;
        const int j = jc * 128 + (t & 127);
        const int sub = t >> 7;                  // 0..7, 8 L-rows each
        const int l0 = lc * 64 + sub * 8;
        float ev[8];
#pragma unroll
        for (int u = 0; u < 8; u++) ev[u] = ldg1(enc + (size_t)(l0 + u) * H + j);
        float acc = 0.f;
#pragma unroll
        for (int u = 0; u < 8; u++) acc += s_attnw[l0 + u] * ev[u];
        red[t] = acc;
        __syncthreads();
        if (t < 512) red[t] += red[t + 512];
        __syncthreads();
        if (t < 256) red[t] += red[t + 256];
        __syncthreads();
        if (t < 128)
            g_attn_partial[lc][jc * 128 + t] = red[t] + red[t + 128];
    }
    gbar(1);

    // ---- Phase C: blocks 0..63: combine + relu (16 rows/block, 2 warps/row)
    if (b < 64) {
        {
            float a = 0.f;
#pragma unroll
            for (int c = 0; c < 8; c++) a += g_attn_partial[c][t];
            s_vec[t] = a;
        }
        __syncthreads();
        const int row = b * 16 + (wid >> 1), half = wid & 1;
        const float* vp = half ? s_vec : s_emb;
        const float4* Wr = (const float4*)(comb_W + (size_t)row * (2 * H) + half * H);
        const float4* sv = (const float4*)vp;
        float4 w[8];
#pragma unroll
        for (int i = 0; i < 8; i++) w[i] = ldg4(Wr + lane + i * 32);
        float acc = 0.f;
#pragma unroll
        for (int i = 0; i < 8; i++) {
            float4 v = sv[lane + i * 32];
            acc += w[i].x * v.x + w[i].y * v.y + w[i].z * v.z + w[i].w * v.w;
        }
        acc = wsum(acc);
        if (lane == 0) red[wid] = acc;
        __syncthreads();
        if (t < 16) {
            const int r = b * 16 + t;
            g_gru_in[r] = fmaxf(red[2 * t] + red[2 * t + 1] + ldg1(comb_b + r), 0.f);
        }
    }
    gbar(2);

    // ---- Phase D: W_ih gate GEMV (3072 warp-jobs over 4736 warps) ----------
    s_vec[t] = g_gru_in[t];
    __syncthreads();
    for (int job = b * NW + wid; job < 3 * H; job += GRID * NW) {
        const float4* Wr = (const float4*)(W_ih + (size_t)job * H);
        const float4* sv = (const float4*)s_vec;
        float4 w[8];
#pragma unroll
        for (int i = 0; i < 8; i++) w[i] = ldg4(Wr + lane + i * 32);
        float acc = 0.f;
#pragma unroll
        for (int i = 0; i < 8; i++) {
            float4 v = sv[lane + i * 32];
            acc += w[i].x * v.x + w[i].y * v.y + w[i].z * v.z + w[i].w * v.w;
        }
        acc = wsum(acc);
        if (lane == 0) g_gates[job] = acc + ldg1(b_ih + job);
    }
    gbar(3);

    // ---- Phase E: redundant GRU elementwise -> s_vec = h_new (per block) ---
    __syncthreads();
    {
        const int i = t;
        const float gxr = g_gates[i],         ghr = g_gates[3 * H + i];
        const float gxz = g_gates[H + i],     ghz = g_gates[4 * H + i];
        const float gxn = g_gates[2 * H + i], ghn = g_gates[5 * H + i];
        const float r = 1.f / (1.f + expf(-(gxr + ghr)));
        const float z = 1.f / (1.f + expf(-(gxz + ghz)));
        const float n = tanhf(gxn + r * ghn);
        s_vec[i] = (1.f - z) * n + z * s_h0[i];
    }
    __syncthreads();

    // ---- Phase E2: big GEMV — pure streaming, no serial epilogue -----------
    const int r0 = b * ROWS_PB;
    const int r1 = (r0 + ROWS_PB < V) ? (r0 + ROWS_PB) : V;
    for (int r = r0 + wid; r < r1; r += NW) {
        const float4* Wr = (const float4*)(out_W + (size_t)r * H);
        const float4* sv = (const float4*)s_vec;
        float4 w[8];
#pragma unroll
        for (int i = 0; i < 8; i++) w[i] = ldg4(Wr + lane + i * 32);
        float acc = 0.f;
#pragma unroll
        for (int i = 0; i < 8; i++) {
            float4 v = sv[lane + i * 32];
            acc += w[i].x * v.x + w[i].y * v.y + w[i].z * v.z + w[i].w * v.w;
        }
        acc = wsum(acc);
        if (lane == 0) g_logits[r] = acc + ldg1(out_b + r);
    }
    gbar(4);

    // ---- Phase F: redundant LSE over all logits (identical tree in every
    //      block -> bitwise-identical lse, no partial exchange), write logp --
    {
        float m = -INFINITY, s = 0.f;
        for (int v = t; v < V; v += TPB) {
            const float xv = g_logits[v];
            const float nm = fmaxf(m, xv);
            s = s * expf(m - nm) + expf(xv - nm);
            m = nm;
        }
        red[t] = m; red2[t] = s;
        __syncthreads();
        for (int o = 512; o; o >>= 1) {
            if (t < o) {
                const float m2 = red[t + o], s2 = red2[t + o];
                const float nm = fmaxf(red[t], m2);
                red2[t] = red2[t] * expf(red[t] - nm) + s2 * expf(m2 - nm);
                red[t] = nm;
            }
            __syncthreads();
        }
        const float lse = red[0] + logf(red2[0]);
        for (int v = r0 + t; v < r1; v += TPB) out[v] = g_logits[v] - lse;
    }
}

extern "C" void kernel_launch(void* const* d_in, const int* in_sizes, int n_in,
                              void* d_out, int out_size) {
    const int*   x      = (const int*)  d_in[0];
    const float* enc    = (const float*)d_in[1];
    const float* hidden = (const float*)d_in[2];
    const float* emb    = (const float*)d_in[3];
    const float* attn_W = (const float*)d_in[4];
    const float* attn_b = (const float*)d_in[5];
    const float* comb_W = (const float*)d_in[6];
    const float* comb_b = (const float*)d_in[7];
    const float* W_ih   = (const float*)d_in[8];
    const float* W_hh   = (const float*)d_in[9];
    const float* b_ih   = (const float*)d_in[10];
    const float* b_hh   = (const float*)d_in[11];
    const float* out_W  = (const float*)d_in[12];
    const float* out_b  = (const float*)d_in[13];
    float* out = (float*)d_out;   // [0,V): logp ; [V,V+L): attn_weights

    k_reset<<<1, 32>>>();
    k_fused<<<GRID, TPB>>>(x, enc, hidden, emb, attn_W, attn_b, comb_W, comb_b,
                           W_ih, W_hh, b_ih, b_hh, out_W, out_b, out);
}

// round 13
// speedup vs baseline: 1.1884x; 1.0009x over previous
#include <cuda_runtime.h>
#include <math.h>
#include <stdint.h>

#define H 1024
#define V 50257
#define L 512
#define GRID 148
#define TPB 1024
#define NW 32                 // warps per block
#define ROWS_PB 340           // ceil(V / GRID)
#define TILE_R 16             // rows per TMA tile (64 KB)
#define NEG_SENT (-1e30f)     // finite LSE identity (avoids -INF - -INF = NaN)

// dynamic smem layout (floats):
//   [0,16384)        buf slot 0   (16 rows x 1024)
//   [16384,32768)    buf slot 1
//   [32768,33792)    s_emb
//   [33792,34816)    s_h0
//   [34816,35840)    s_vec
//   [35840,36352)    s_attnw
//   [36352,37376)    red
//   [37376,38400)    red2
#define DSMEM_FLOATS 38400
#define DSMEM_BYTES (DSMEM_FLOATS * 4)

// ---------------- scratch (device globals; no allocations allowed) ----------
__device__ float g_qpart[2048];          // attn score quarter-partials
__device__ float g_attn_partial[8][H];
__device__ float g_gru_in[H];
__device__ float g_gates[6 * H];         // [0,3H)=gx, [3H,6H)=gh
__device__ float g_logits[V];
__device__ float g_pm[GRID], g_ps[GRID];
__device__ unsigned g_bars[8];

__global__ void k_reset() {
    if (threadIdx.x < 8) g_bars[threadIdx.x] = 0u;
}

__device__ __forceinline__ float4 ldg4(const float4* p) {
    float4 v;
    asm volatile("ld.global.nc.v4.f32 {%0,%1,%2,%3},[%4];"
                 : "=f"(v.x), "=f"(v.y), "=f"(v.z), "=f"(v.w) : "l"(p));
    return v;
}
__device__ __forceinline__ float ldg1(const float* p) {
    float v;
    asm volatile("ld.global.nc.f32 %0,[%1];" : "=f"(v) : "l"(p));
    return v;
}
__device__ __forceinline__ float wsum(float v) {
#pragma unroll
    for (int o = 16; o; o >>= 1) v += __shfl_down_sync(0xffffffffu, v, o);
    return v;
}
__device__ __forceinline__ uint32_t s2u(const void* p) {
    uint32_t a;
    asm("{ .reg .u64 t; cvta.to.shared.u64 t, %1; cvt.u32.u64 %0, t; }"
        : "=r"(a) : "l"(p));
    return a;
}
__device__ __forceinline__ void mbar_init(uint32_t mb, uint32_t cnt) {
    asm volatile("mbarrier.init.shared.b64 [%0], %1;" :: "r"(mb), "r"(cnt) : "memory");
}
__device__ __forceinline__ void mbar_expect_tx(uint32_t mb, uint32_t bytes) {
    asm volatile("mbarrier.arrive.expect_tx.shared.b64 _, [%0], %1;"
                 :: "r"(mb), "r"(bytes) : "memory");
}
__device__ __forceinline__ void tma_1d(uint32_t dst, const void* src,
                                       uint32_t bytes, uint32_t mb) {
    asm volatile("cp.async.bulk.shared::cta.global.mbarrier::complete_tx::bytes "
                 "[%0], [%1], %2, [%3];"
                 :: "r"(dst), "l"(src), "r"(bytes), "r"(mb) : "memory");
}
__device__ __forceinline__ void mbar_wait(uint32_t mb, uint32_t parity) {
    asm volatile("{\n\t.reg .pred p;\n\t"
                 "W_%=:\n\t"
                 "mbarrier.try_wait.parity.acquire.cta.shared::cta.b64 p, [%0], %1, 0x989680;\n\t"
                 "@!p bra W_%=;\n\t}"
                 :: "r"(mb), "r"(parity) : "memory");
}

// grid barrier: 148 CTAs, 1/SM, all resident in wave 1 -> spin safe.
__device__ __forceinline__ void gbar(int ph) {
    __syncthreads();
    if (threadIdx.x == 0) {
        __threadfence();
        unsigned arrived = atomicAdd(&g_bars[ph], 1u) + 1u;
        if (arrived < GRID) {
            volatile unsigned* p = &g_bars[ph];
            while (*p < GRID) { __nanosleep(64); }
        }
        __threadfence();
    }
    __syncthreads();
}

__global__ void __launch_bounds__(TPB, 1)
k_fused(const int* __restrict__ x,
        const float* __restrict__ enc,
        const float* __restrict__ hidden,
        const float* __restrict__ emb,
        const float* __restrict__ attn_W,
        const float* __restrict__ attn_b,
        const float* __restrict__ comb_W,
        const float* __restrict__ comb_b,
        const float* __restrict__ W_ih,
        const float* __restrict__ W_hh,
        const float* __restrict__ b_ih,
        const float* __restrict__ b_hh,
        const float* __restrict__ out_W,
        const float* __restrict__ out_b,
        float* __restrict__ out) {
    extern __shared__ float dsm[];
    float* bufs[2] = { dsm, dsm + TILE_R * H };
    float* s_emb   = dsm + 2 * TILE_R * H;
    float* s_h0    = s_emb + H;
    float* s_vec   = s_h0 + H;
    float* s_attnw = s_vec + H;
    float* red     = s_attnw + L;
    float* red2    = red + 1024;
    __shared__ uint64_t mbars[2];
    __shared__ float prow[2][32];

    const int t = threadIdx.x, b = blockIdx.x;
    const int wid = t >> 5, lane = t & 31;

    // preload emb row + hidden into shared; init TMA mbarriers
    {
        const float* er = emb + (size_t)x[0] * H;
        s_emb[t] = ldg1(er + t);
        s_h0[t] = ldg1(hidden + t);
        if (t == 0) { mbar_init(s2u(&mbars[0]), 1); mbar_init(s2u(&mbars[1]), 1); }
        __syncthreads();
    }

    // ---- Phase A: attn-score quarter partials (2048 jobs)
    //      + W_hh gate GEMV (3072 jobs) — depend only on inputs --------------
    for (int job = b * NW + wid; job < 5120; job += GRID * NW) {
        if (job < 2048) {
            const int row = job >> 2, q = job & 3;
            const float* vp = (q < 2) ? (s_emb + q * 512) : (s_h0 + (q - 2) * 512);
            const float4* Wr = (const float4*)(attn_W + (size_t)row * (2 * H) + q * 512);
            const float4* sv = (const float4*)vp;
            float4 w[4];
#pragma unroll
            for (int i = 0; i < 4; i++) w[i] = ldg4(Wr + lane + i * 32);
            float acc = 0.f;
#pragma unroll
            for (int i = 0; i < 4; i++) {
                float4 v = sv[lane + i * 32];
                acc += w[i].x * v.x + w[i].y * v.y + w[i].z * v.z + w[i].w * v.w;
            }
            acc = wsum(acc);
            if (lane == 0) g_qpart[job] = acc;
        } else {
            const int r = job - 2048;
            const float4* Wr = (const float4*)(W_hh + (size_t)r * H);
            const float4* sv = (const float4*)s_h0;
            float4 w[8];
#pragma unroll
            for (int i = 0; i < 8; i++) w[i] = ldg4(Wr + lane + i * 32);
            float acc = 0.f;
#pragma unroll
            for (int i = 0; i < 8; i++) {
                float4 v = sv[lane + i * 32];
                acc += w[i].x * v.x + w[i].y * v.y + w[i].z * v.z + w[i].w * v.w;
            }
            acc = wsum(acc);
            if (lane == 0) g_gates[3 * H + r] = acc + ldg1(b_hh + r);
        }
    }
    gbar(0);

    // ---- Phase B: blocks 0..63: redundant softmax (L=512), then attn apply -
    if (b < 64) {
        float sc = NEG_SENT;
        if (t < L)
            sc = g_qpart[4 * t] + g_qpart[4 * t + 1] + g_qpart[4 * t + 2]
               + g_qpart[4 * t + 3] + ldg1(attn_b + t);
        red[t] = sc;
        __syncthreads();
        for (int o = 512; o; o >>= 1) {
            if (t < o) red[t] = fmaxf(red[t], red[t + o]);
            __syncthreads();
        }
        const float m = red[0];
        __syncthreads();
        const float e = (t < L) ? expf(sc - m) : 0.f;
        red[t] = e;
        __syncthreads();
        for (int o = 512; o; o >>= 1) {
            if (t < o) red[t] += red[t + o];
            __syncthreads();
        }
        if (t < L) {
            const float aw = e / red[0];
            s_attnw[t] = aw;
            if (b == 0) out[V + t] = aw;
        }
        __syncthreads();

        const int lc = b >> 3, jc = b & 7;
        const int j = jc * 128 + (t & 127);
        const int sub = t >> 7;                  // 0..7, 8 L-rows each
        const int l0 = lc * 64 + sub * 8;
        float ev[8];
#pragma unroll
        for (int u = 0; u < 8; u++) ev[u] = ldg1(enc + (size_t)(l0 + u) * H + j);
        float acc = 0.f;
#pragma unroll
        for (int u = 0; u < 8; u++) acc += s_attnw[l0 + u] * ev[u];
        red[t] = acc;
        __syncthreads();
        if (t < 512) red[t] += red[t + 512];
        __syncthreads();
        if (t < 256) red[t] += red[t + 256];
        __syncthreads();
        if (t < 128)
            g_attn_partial[lc][jc * 128 + t] = red[t] + red[t + 128];
    }
    gbar(1);

    // ---- Phase C: blocks 0..63: combine + relu (16 rows/block, 2 warps/row)
    if (b < 64) {
        {
            float a = 0.f;
#pragma unroll
            for (int c = 0; c < 8; c++) a += g_attn_partial[c][t];
            s_vec[t] = a;
        }
        __syncthreads();
        const int row = b * 16 + (wid >> 1), half = wid & 1;
        const float* vp = half ? s_vec : s_emb;
        const float4* Wr = (const float4*)(comb_W + (size_t)row * (2 * H) + half * H);
        const float4* sv = (const float4*)vp;
        float4 w[8];
#pragma unroll
        for (int i = 0; i < 8; i++) w[i] = ldg4(Wr + lane + i * 32);
        float acc = 0.f;
#pragma unroll
        for (int i = 0; i < 8; i++) {
            float4 v = sv[lane + i * 32];
            acc += w[i].x * v.x + w[i].y * v.y + w[i].z * v.z + w[i].w * v.w;
        }
        acc = wsum(acc);
        if (lane == 0) red[wid] = acc;
        __syncthreads();
        if (t < 16) {
            const int r = b * 16 + t;
            g_gru_in[r] = fmaxf(red[2 * t] + red[2 * t + 1] + ldg1(comb_b + r), 0.f);
        }
    }
    gbar(2);

    // ---- Phase D: W_ih gate GEMV (3072 warp-jobs) --------------------------
    s_vec[t] = g_gru_in[t];
    __syncthreads();
    for (int job = b * NW + wid; job < 3 * H; job += GRID * NW) {
        const float4* Wr = (const float4*)(W_ih + (size_t)job * H);
        const float4* sv = (const float4*)s_vec;
        float4 w[8];
#pragma unroll
        for (int i = 0; i < 8; i++) w[i] = ldg4(Wr + lane + i * 32);
        float acc = 0.f;
#pragma unroll
        for (int i = 0; i < 8; i++) {
            float4 v = sv[lane + i * 32];
            acc += w[i].x * v.x + w[i].y * v.y + w[i].z * v.z + w[i].w * v.w;
        }
        acc = wsum(acc);
        if (lane == 0) g_gates[job] = acc + ldg1(b_ih + job);
    }
    gbar(3);

    // ---- Phase E: redundant GRU elementwise -> s_vec = h_new ---------------
    __syncthreads();
    {
        const int i = t;
        const float gxr = g_gates[i],         ghr = g_gates[3 * H + i];
        const float gxz = g_gates[H + i],     ghz = g_gates[4 * H + i];
        const float gxn = g_gates[2 * H + i], ghn = g_gates[5 * H + i];
        const float r = 1.f / (1.f + expf(-(gxr + ghr)));
        const float z = 1.f / (1.f + expf(-(gxz + ghz)));
        const float n = tanhf(gxn + r * ghn);
        s_vec[i] = (1.f - z) * n + z * s_h0[i];
    }
    __syncthreads();

    // ---- Phase E2: big GEMV via TMA double-buffered tile pipeline ----------
    const int r0 = b * ROWS_PB;
    const int r1 = (r0 + ROWS_PB < V) ? (r0 + ROWS_PB) : V;
    const int nrows = r1 - r0;
    const int ntiles = (nrows + TILE_R - 1) / TILE_R;
    const uint32_t mbu[2] = { s2u(&mbars[0]), s2u(&mbars[1]) };
    const uint32_t bufu[2] = { s2u(bufs[0]), s2u(bufs[1]) };

    if (t == 0) {
        // prefetch tiles 0 and 1
        {
            const uint32_t bytes = (uint32_t)((nrows < TILE_R ? nrows : TILE_R) * H * 4);
            mbar_expect_tx(mbu[0], bytes);
            tma_1d(bufu[0], out_W + (size_t)r0 * H, bytes, mbu[0]);
        }
        if (ntiles > 1) {
            const int rws = (nrows - TILE_R < TILE_R) ? nrows - TILE_R : TILE_R;
            const uint32_t bytes = (uint32_t)(rws * H * 4);
            mbar_expect_tx(mbu[1], bytes);
            tma_1d(bufu[1], out_W + (size_t)(r0 + TILE_R) * H, bytes, mbu[1]);
        }
    }

    for (int k = 0; k < ntiles; k++) {
        const int slot = k & 1;
        const uint32_t par = (k >> 1) & 1;
        mbar_wait(mbu[slot], par);

        const int rows = (nrows - k * TILE_R < TILE_R) ? nrows - k * TILE_R : TILE_R;
        const int row = wid >> 1, half = wid & 1;
        float part = 0.f;
        if (row < rows) {
            const float4* bp = (const float4*)(bufs[slot] + row * H + half * 512);
            const float4* sp = (const float4*)(s_vec + half * 512);
#pragma unroll
            for (int i = 0; i < 4; i++) {
                const float4 w = bp[lane + i * 32];
                const float4 v = sp[lane + i * 32];
                part += w.x * v.x + w.y * v.y + w.z * v.z + w.w * v.w;
            }
            part = wsum(part);
        }
        if (lane == 0) prow[slot][wid] = part;
        __syncthreads();
        // refill this slot for tile k+2
        if (t == 0 && k + 2 < ntiles) {
            const int kr = k + 2;
            const int rws = (nrows - kr * TILE_R < TILE_R) ? nrows - kr * TILE_R : TILE_R;
            const uint32_t bytes = (uint32_t)(rws * H * 4);
            mbar_expect_tx(mbu[slot], bytes);
            tma_1d(bufu[slot], out_W + (size_t)(r0 + kr * TILE_R) * H, bytes, mbu[slot]);
        }
        if (t < rows) {
            const int r = r0 + k * TILE_R + t;
            g_logits[r] = prow[slot][2 * t] + prow[slot][2 * t + 1] + ldg1(out_b + r);
        }
        __syncthreads();
    }

    // per-block LSE partial over own rows (L2-hot); finite sentinel, no NaN
    {
        red[t]  = (t < nrows) ? g_logits[r0 + t] : NEG_SENT;
        red2[t] = (t < nrows) ? 1.f : 0.f;
        __syncthreads();
        for (int o = 512; o; o >>= 1) {
            if (t < o) {
                const float m2 = red[t + o], s2 = red2[t + o];
                const float nm = fmaxf(red[t], m2);
                red2[t] = red2[t] * expf(red[t] - nm) + s2 * expf(m2 - nm);
                red[t] = nm;
            }
            __syncthreads();
        }
        if (t == 0) { g_pm[b] = red[0]; g_ps[b] = red2[0]; }
    }
    gbar(4);

    // ---- Phase F: redundant combine of 148 partials (identical tree) -------
    {
        if (t < 256) {
            red[t]  = (t < GRID) ? g_pm[t] : NEG_SENT;
            red2[t] = (t < GRID) ? g_ps[t] : 0.f;
        }
        __syncthreads();
        for (int o = 128; o; o >>= 1) {
            if (t < o) {
                const float m2 = red[t + o], s2 = red2[t + o];
                const float nm = fmaxf(red[t], m2);
                red2[t] = red2[t] * expf(red[t] - nm) + s2 * expf(m2 - nm);
                red[t] = nm;
            }
            __syncthreads();
        }
        const float lse = red[0] + logf(red2[0]);
        if (t < nrows) out[r0 + t] = g_logits[r0 + t] - lse;
    }
}

extern "C" void kernel_launch(void* const* d_in, const int* in_sizes, int n_in,
                              void* d_out, int out_size) {
    const int*   x      = (const int*)  d_in[0];
    const float* enc    = (const float*)d_in[1];
    const float* hidden = (const float*)d_in[2];
    const float* emb    = (const float*)d_in[3];
    const float* attn_W = (const float*)d_in[4];
    const float* attn_b = (const float*)d_in[5];
    const float* comb_W = (const float*)d_in[6];
    const float* comb_b = (const float*)d_in[7];
    const float* W_ih   = (const float*)d_in[8];
    const float* W_hh   = (const float*)d_in[9];
    const float* b_ih   = (const float*)d_in[10];
    const float* b_hh   = (const float*)d_in[11];
    const float* out_W  = (const float*)d_in[12];
    const float* out_b  = (const float*)d_in[13];
    float* out = (float*)d_out;   // [0,V): logp ; [V,V+L): attn_weights

    cudaFuncSetAttribute(k_fused, cudaFuncAttributeMaxDynamicSharedMemorySize,
                         DSMEM_BYTES);
    k_reset<<<1, 32>>>();
    k_fused<<<GRID, TPB, DSMEM_BYTES>>>(x, enc, hidden, emb, attn_W, attn_b,
                                        comb_W, comb_b, W_ih, W_hh, b_ih, b_hh,
                                        out_W, out_b, out);
}

// round 14
// speedup vs baseline: 1.2561x; 1.0570x over previous
#include <cuda_runtime.h>
#include <math.h>
#include <stdint.h>

#define H 1024
#define V 50257
#define L 512
#define GRID 148
#define TPB 1024
#define NW 32                 // warps per block
#define ROWS_PB 340           // ceil(V / GRID)
#define TILE_R 16             // rows per TMA tile (64 KB)
#define RING 3                // ring depth (3 x 64 KB in flight)
#define NEG_SENT (-1e30f)     // finite LSE identity

// dynamic smem layout (floats):
//   [0, 3*16384)                     ring buffers
//   then s_emb[1024], s_h0[1024], s_vec[1024], s_attnw[512],
//        red[1024], red2[1024], s_outb[384], s_logits[384]
#define RING_FLOATS (RING * TILE_R * H)
#define DSMEM_FLOATS (RING_FLOATS + 1024 * 3 + 512 + 1024 * 2 + 384 * 2)
#define DSMEM_BYTES (DSMEM_FLOATS * 4)

// ---------------- scratch (device globals; no allocations allowed) ----------
__device__ float g_qpart[2048];          // attn score quarter-partials
__device__ float g_attn_partial[8][H];
__device__ float g_gru_in[H];
__device__ float g_gates[6 * H];         // [0,3H)=gx, [3H,6H)=gh
__device__ float g_pm[GRID], g_ps[GRID];
__device__ unsigned g_bars[8];

__global__ void k_reset() {
    if (threadIdx.x < 8) g_bars[threadIdx.x] = 0u;
}

__device__ __forceinline__ float4 ldg4(const float4* p) {
    float4 v;
    asm volatile("ld.global.nc.v4.f32 {%0,%1,%2,%3},[%4];"
                 : "=f"(v.x), "=f"(v.y), "=f"(v.z), "=f"(v.w) : "l"(p));
    return v;
}
__device__ __forceinline__ float ldg1(const float* p) {
    float v;
    asm volatile("ld.global.nc.f32 %0,[%1];" : "=f"(v) : "l"(p));
    return v;
}
__device__ __forceinline__ float wsum(float v) {
#pragma unroll
    for (int o = 16; o; o >>= 1) v += __shfl_down_sync(0xffffffffu, v, o);
    return v;
}
__device__ __forceinline__ uint32_t s2u(const void* p) {
    uint32_t a;
    asm("{ .reg .u64 t; cvta.to.shared.u64 t, %1; cvt.u32.u64 %0, t; }"
        : "=r"(a) : "l"(p));
    return a;
}
__device__ __forceinline__ void mbar_init(uint32_t mb, uint32_t cnt) {
    asm volatile("mbarrier.init.shared.b64 [%0], %1;" :: "r"(mb), "r"(cnt) : "memory");
}
__device__ __forceinline__ void mbar_expect_tx(uint32_t mb, uint32_t bytes) {
    asm volatile("mbarrier.arrive.expect_tx.shared.b64 _, [%0], %1;"
                 :: "r"(mb), "r"(bytes) : "memory");
}
__device__ __forceinline__ void tma_1d(uint32_t dst, const void* src,
                                       uint32_t bytes, uint32_t mb) {
    asm volatile("cp.async.bulk.shared::cta.global.mbarrier::complete_tx::bytes "
                 "[%0], [%1], %2, [%3];"
                 :: "r"(dst), "l"(src), "r"(bytes), "r"(mb) : "memory");
}
__device__ __forceinline__ void mbar_wait(uint32_t mb, uint32_t parity) {
    asm volatile("{\n\t.reg .pred p;\n\t"
                 "W_%=:\n\t"
                 "mbarrier.try_wait.parity.acquire.cta.shared::cta.b64 p, [%0], %1, 0x989680;\n\t"
                 "@!p bra W_%=;\n\t}"
                 :: "r"(mb), "r"(parity) : "memory");
}

// grid barrier: 148 CTAs, 1/SM, all resident in wave 1 -> spin safe.
__device__ __forceinline__ void gbar(int ph) {
    __syncthreads();
    if (threadIdx.x == 0) {
        __threadfence();
        unsigned arrived = atomicAdd(&g_bars[ph], 1u) + 1u;
        if (arrived < GRID) {
            volatile unsigned* p = &g_bars[ph];
            while (*p < GRID) { __nanosleep(64); }
        }
        __threadfence();
    }
    __syncthreads();
}

__global__ void __launch_bounds__(TPB, 1)
k_fused(const int* __restrict__ x,
        const float* __restrict__ enc,
        const float* __restrict__ hidden,
        const float* __restrict__ emb,
        const float* __restrict__ attn_W,
        const float* __restrict__ attn_b,
        const float* __restrict__ comb_W,
        const float* __restrict__ comb_b,
        const float* __restrict__ W_ih,
        const float* __restrict__ W_hh,
        const float* __restrict__ b_ih,
        const float* __restrict__ b_hh,
        const float* __restrict__ out_W,
        const float* __restrict__ out_b,
        float* __restrict__ out) {
    extern __shared__ float dsm[];
    float* s_emb    = dsm + RING_FLOATS;
    float* s_h0     = s_emb + H;
    float* s_vec    = s_h0 + H;
    float* s_attnw  = s_vec + H;
    float* red      = s_attnw + L;
    float* red2     = red + 1024;
    float* s_outb   = red2 + 1024;
    float* s_logits = s_outb + 384;
    __shared__ uint64_t mbars[RING];
    __shared__ float prow[TILE_R][2];

    const int t = threadIdx.x, b = blockIdx.x;
    const int wid = t >> 5, lane = t & 31;

    const int r0 = b * ROWS_PB;
    const int r1 = (r0 + ROWS_PB < V) ? (r0 + ROWS_PB) : V;
    const int nrows = r1 - r0;
    const int ntiles = (nrows + TILE_R - 1) / TILE_R;

    // ---- preamble: init mbarriers, kick off first RING TMA fills (out_W
    //      depends on nothing -> overlaps with all early phases), preload
    //      emb row / hidden / out_b slice into shared --------------------
    if (t == 0) {
#pragma unroll
        for (int s = 0; s < RING; s++) mbar_init(s2u(&mbars[s]), 1);
    }
    __syncthreads();
    if (t == 0) {
        const int nf = (ntiles < RING) ? ntiles : RING;
        for (int s = 0; s < nf; s++) {
            const int rws = (nrows - s * TILE_R < TILE_R) ? nrows - s * TILE_R : TILE_R;
            const uint32_t bytes = (uint32_t)(rws * H * 4);
            mbar_expect_tx(s2u(&mbars[s]), bytes);
            tma_1d(s2u(dsm + s * TILE_R * H), out_W + (size_t)(r0 + s * TILE_R) * H,
                   bytes, s2u(&mbars[s]));
        }
    }
    {
        const float* er = emb + (size_t)x[0] * H;
        s_emb[t] = ldg1(er + t);
        s_h0[t] = ldg1(hidden + t);
        if (t < nrows) s_outb[t] = ldg1(out_b + r0 + t);
        __syncthreads();
    }

    // ---- Phase A: attn-score quarter partials (2048 jobs)
    //      + W_hh gate GEMV (3072 jobs) — depend only on inputs --------------
    for (int job = b * NW + wid; job < 5120; job += GRID * NW) {
        if (job < 2048) {
            const int row = job >> 2, q = job & 3;
            const float* vp = (q < 2) ? (s_emb + q * 512) : (s_h0 + (q - 2) * 512);
            const float4* Wr = (const float4*)(attn_W + (size_t)row * (2 * H) + q * 512);
            const float4* sv = (const float4*)vp;
            float4 w[4];
#pragma unroll
            for (int i = 0; i < 4; i++) w[i] = ldg4(Wr + lane + i * 32);
            float acc = 0.f;
#pragma unroll
            for (int i = 0; i < 4; i++) {
                float4 v = sv[lane + i * 32];
                acc += w[i].x * v.x + w[i].y * v.y + w[i].z * v.z + w[i].w * v.w;
            }
            acc = wsum(acc);
            if (lane == 0) g_qpart[job] = acc;
        } else {
            const int r = job - 2048;
            const float4* Wr = (const float4*)(W_hh + (size_t)r * H);
            const float4* sv = (const float4*)s_h0;
            float4 w[8];
#pragma unroll
            for (int i = 0; i < 8; i++) w[i] = ldg4(Wr + lane + i * 32);
            float acc = 0.f;
#pragma unroll
            for (int i = 0; i < 8; i++) {
                float4 v = sv[lane + i * 32];
                acc += w[i].x * v.x + w[i].y * v.y + w[i].z * v.z + w[i].w * v.w;
            }
            acc = wsum(acc);
            if (lane == 0) g_gates[3 * H + r] = acc + ldg1(b_hh + r);
        }
    }
    gbar(0);

    // ---- Phase B: blocks 0..63: redundant softmax (L=512), then attn apply -
    if (b < 64) {
        float sc = NEG_SENT;
        if (t < L)
            sc = g_qpart[4 * t] + g_qpart[4 * t + 1] + g_qpart[4 * t + 2]
               + g_qpart[4 * t + 3] + ldg1(attn_b + t);
        red[t] = sc;
        __syncthreads();
        for (int o = 512; o; o >>= 1) {
            if (t < o) red[t] = fmaxf(red[t], red[t + o]);
            __syncthreads();
        }
        const float m = red[0];
        __syncthreads();
        const float e = (t < L) ? expf(sc - m) : 0.f;
        red[t] = e;
        __syncthreads();
        for (int o = 512; o; o >>= 1) {
            if (t < o) red[t] += red[t + o];
            __syncthreads();
        }
        if (t < L) {
            const float aw = e / red[0];
            s_attnw[t] = aw;
            if (b == 0) out[V + t] = aw;
        }
        __syncthreads();

        const int lc = b >> 3, jc = b & 7;
        const int j = jc * 128 + (t & 127);
        const int sub = t >> 7;                  // 0..7, 8 L-rows each
        const int l0 = lc * 64 + sub * 8;
        float ev[8];
#pragma unroll
        for (int u = 0; u < 8; u++) ev[u] = ldg1(enc + (size_t)(l0 + u) * H + j);
        float acc = 0.f;
#pragma unroll
        for (int u = 0; u < 8; u++) acc += s_attnw[l0 + u] * ev[u];
        red[t] = acc;
        __syncthreads();
        if (t < 512) red[t] += red[t + 512];
        __syncthreads();
        if (t < 256) red[t] += red[t + 256];
        __syncthreads();
        if (t < 128)
            g_attn_partial[lc][jc * 128 + t] = red[t] + red[t + 128];
    }
    gbar(1);

    // ---- Phase C: blocks 0..63: combine + relu (16 rows/block, 2 warps/row)
    if (b < 64) {
        {
            float a = 0.f;
#pragma unroll
            for (int c = 0; c < 8; c++) a += g_attn_partial[c][t];
            s_vec[t] = a;
        }
        __syncthreads();
        const int row = b * 16 + (wid >> 1), half = wid & 1;
        const float* vp = half ? s_vec : s_emb;
        const float4* Wr = (const float4*)(comb_W + (size_t)row * (2 * H) + half * H);
        const float4* sv = (const float4*)vp;
        float4 w[8];
#pragma unroll
        for (int i = 0; i < 8; i++) w[i] = ldg4(Wr + lane + i * 32);
        float acc = 0.f;
#pragma unroll
        for (int i = 0; i < 8; i++) {
            float4 v = sv[lane + i * 32];
            acc += w[i].x * v.x + w[i].y * v.y + w[i].z * v.z + w[i].w * v.w;
        }
        acc = wsum(acc);
        if (lane == 0) red[wid] = acc;
        __syncthreads();
        if (t < 16) {
            const int r = b * 16 + t;
            g_gru_in[r] = fmaxf(red[2 * t] + red[2 * t + 1] + ldg1(comb_b + r), 0.f);
        }
    }
    gbar(2);

    // ---- Phase D: W_ih gate GEMV (3072 warp-jobs) --------------------------
    s_vec[t] = g_gru_in[t];
    __syncthreads();
    for (int job = b * NW + wid; job < 3 * H; job += GRID * NW) {
        const float4* Wr = (const float4*)(W_ih + (size_t)job * H);
        const float4* sv = (const float4*)s_vec;
        float4 w[8];
#pragma unroll
        for (int i = 0; i < 8; i++) w[i] = ldg4(Wr + lane + i * 32);
        float acc = 0.f;
#pragma unroll
        for (int i = 0; i < 8; i++) {
            float4 v = sv[lane + i * 32];
            acc += w[i].x * v.x + w[i].y * v.y + w[i].z * v.z + w[i].w * v.w;
        }
        acc = wsum(acc);
        if (lane == 0) g_gates[job] = acc + ldg1(b_ih + job);
    }
    gbar(3);

    // ---- Phase E: redundant GRU elementwise -> s_vec = h_new ---------------
    __syncthreads();
    {
        const int i = t;
        const float gxr = g_gates[i],         ghr = g_gates[3 * H + i];
        const float gxz = g_gates[H + i],     ghz = g_gates[4 * H + i];
        const float gxn = g_gates[2 * H + i], ghn = g_gates[5 * H + i];
        const float r = 1.f / (1.f + expf(-(gxr + ghr)));
        const float z = 1.f / (1.f + expf(-(gxz + ghz)));
        const float n = tanhf(gxn + r * ghn);
        s_vec[i] = (1.f - z) * n + z * s_h0[i];
    }
    __syncthreads();

    // ---- Phase E2: big GEMV via 3-deep TMA ring (fills started in preamble)
    {
        const int row = wid >> 1, half = wid & 1;
        const float4* svq = (const float4*)(s_vec + half * 512);
        float4 va[4];
#pragma unroll
        for (int i = 0; i < 4; i++) va[i] = svq[lane + i * 32];

        for (int k = 0; k < ntiles; k++) {
            const int slot = k % RING;
            const uint32_t par = (uint32_t)((k / RING) & 1);
            mbar_wait(s2u(&mbars[slot]), par);

            const int rows = (nrows - k * TILE_R < TILE_R) ? nrows - k * TILE_R : TILE_R;
            float part = 0.f;
            if (row < rows) {
                const float4* bp = (const float4*)(dsm + slot * TILE_R * H + row * H + half * 512);
#pragma unroll
                for (int i = 0; i < 4; i++) {
                    const float4 w = bp[lane + i * 32];
                    part += w.x * va[i].x + w.y * va[i].y + w.z * va[i].z + w.w * va[i].w;
                }
                part = wsum(part);
            }
            if (lane == 0 && row < TILE_R) prow[row][half] = part;
            __syncthreads();
            // all warps done reading this slot -> refill it for tile k+RING
            if (t == 0 && k + RING < ntiles) {
                const int kr = k + RING;
                const int rws = (nrows - kr * TILE_R < TILE_R) ? nrows - kr * TILE_R : TILE_R;
                const uint32_t bytes = (uint32_t)(rws * H * 4);
                mbar_expect_tx(s2u(&mbars[slot]), bytes);
                tma_1d(s2u(dsm + slot * TILE_R * H), out_W + (size_t)(r0 + kr * TILE_R) * H,
                       bytes, s2u(&mbars[slot]));
            }
            if (t < rows)
                s_logits[k * TILE_R + t] = prow[t][0] + prow[t][1] + s_outb[k * TILE_R + t];
            __syncthreads();
        }
    }

    // per-block LSE partial over own rows (smem-resident logits)
    {
        red[t]  = (t < nrows) ? s_logits[t] : NEG_SENT;
        red2[t] = (t < nrows) ? 1.f : 0.f;
        __syncthreads();
        for (int o = 512; o; o >>= 1) {
            if (t < o) {
                const float m2 = red[t + o], s2 = red2[t + o];
                const float nm = fmaxf(red[t], m2);
                red2[t] = red2[t] * expf(red[t] - nm) + s2 * expf(m2 - nm);
                red[t] = nm;
            }
            __syncthreads();
        }
        if (t == 0) { g_pm[b] = red[0]; g_ps[b] = red2[0]; }
    }
    gbar(4);

    // ---- Phase F: redundant combine of 148 partials (identical tree) -------
    {
        if (t < 256) {
            red[t]  = (t < GRID) ? g_pm[t] : NEG_SENT;
            red2[t] = (t < GRID) ? g_ps[t] : 0.f;
        }
        __syncthreads();
        for (int o = 128; o; o >>= 1) {
            if (t < o) {
                const float m2 = red[t + o], s2 = red2[t + o];
                const float nm = fmaxf(red[t], m2);
                red2[t] = red2[t] * expf(red[t] - nm) + s2 * expf(m2 - nm);
                red[t] = nm;
            }
            __syncthreads();
        }
        const float lse = red[0] + logf(red2[0]);
        if (t < nrows) out[r0 + t] = s_logits[t] - lse;
    }
}

extern "C" void kernel_launch(void* const* d_in, const int* in_sizes, int n_in,
                              void* d_out, int out_size) {
    const int*   x      = (const int*)  d_in[0];
    const float* enc    = (const float*)d_in[1];
    const float* hidden = (const float*)d_in[2];
    const float* emb    = (const float*)d_in[3];
    const float* attn_W = (const float*)d_in[4];
    const float* attn_b = (const float*)d_in[5];
    const float* comb_W = (const float*)d_in[6];
    const float* comb_b = (const float*)d_in[7];
    const float* W_ih   = (const float*)d_in[8];
    const float* W_hh   = (const float*)d_in[9];
    const float* b_ih   = (const float*)d_in[10];
    const float* b_hh   = (const float*)d_in[11];
    const float* out_W  = (const float*)d_in[12];
    const float* out_b  = (const float*)d_in[13];
    float* out = (float*)d_out;   // [0,V): logp ; [V,V+L): attn_weights

    cudaFuncSetAttribute(k_fused, cudaFuncAttributeMaxDynamicSharedMemorySize,
                         DSMEM_BYTES);
    k_reset<<<1, 32>>>();
    k_fused<<<GRID, TPB, DSMEM_BYTES>>>(x, enc, hidden, emb, attn_W, attn_b,
                                        comb_W, comb_b, W_ih, W_hh, b_ih, b_hh,
                                        out_W, out_b, out);
}

// round 16
// speedup vs baseline: 1.4398x; 1.1462x over previous
#include <cuda_runtime.h>
#include <math.h>
#include <stdint.h>

#define H 1024
#define V 50257
#define L 512
#define GRID 148
#define TPB 1024
#define NW 32                  // warps per block
#define ROWS_PB 340            // ceil(V / GRID)
#define STICKY_ROWS 108        // per-block out_W rows pinned L2-sticky (~64 MB total)
#define NEG_SENT (-1e30f)      // finite LSE identity

// ---------------- scratch (device globals; no allocations allowed) ----------
__device__ float g_qpart[2048];          // attn score quarter-partials
__device__ float g_attn_partial[8][H];
__device__ float g_gru_in[H];
__device__ float g_gates[6 * H];         // [0,3H)=gx, [3H,6H)=gh
__device__ float g_pm[GRID], g_ps[GRID];
__device__ unsigned g_bars[8];

__global__ void k_reset() {
    if (threadIdx.x < 8) g_bars[threadIdx.x] = 0u;
}

// ---- cache-policy based hinted loads (createpolicy + L2::cache_hint form,
//      which ptxas accepts for .v4.f32 / .f32 unlike inline evict_* ) -------
__device__ __forceinline__ uint64_t mkpol_last() {
    uint64_t p;
    asm("createpolicy.fractional.L2::evict_last.b64 %0, 1.0;" : "=l"(p));
    return p;
}
__device__ __forceinline__ uint64_t mkpol_first() {
    uint64_t p;
    asm("createpolicy.fractional.L2::evict_first.b64 %0, 1.0;" : "=l"(p));
    return p;
}
__device__ __forceinline__ float4 ldg4_pol(const float4* p, uint64_t pol) {
    float4 v;
    asm volatile("ld.global.nc.L2::cache_hint.v4.f32 {%0,%1,%2,%3},[%4],%5;"
                 : "=f"(v.x), "=f"(v.y), "=f"(v.z), "=f"(v.w) : "l"(p), "l"(pol));
    return v;
}
__device__ __forceinline__ float ldg1_pol(const float* p, uint64_t pol) {
    float v;
    asm volatile("ld.global.nc.L2::cache_hint.f32 %0,[%1],%2;"
                 : "=f"(v) : "l"(p), "l"(pol));
    return v;
}
__device__ __forceinline__ float ldg1(const float* p) {
    float v;
    asm volatile("ld.global.nc.f32 %0,[%1];" : "=f"(v) : "l"(p));
    return v;
}
__device__ __forceinline__ float wsum(float v) {
#pragma unroll
    for (int o = 16; o; o >>= 1) v += __shfl_down_sync(0xffffffffu, v, o);
    return v;
}

// grid barrier: 148 CTAs, 1/SM, all resident in wave 1 -> spin safe.
__device__ __forceinline__ void gbar(int ph) {
    __syncthreads();
    if (threadIdx.x == 0) {
        __threadfence();
        unsigned arrived = atomicAdd(&g_bars[ph], 1u) + 1u;
        if (arrived < GRID) {
            volatile unsigned* p = &g_bars[ph];
            while (*p < GRID) { __nanosleep(64); }
        }
        __threadfence();
    }
    __syncthreads();
}

__global__ void __launch_bounds__(TPB, 1)
k_fused(const int* __restrict__ x,
        const float* __restrict__ enc,
        const float* __restrict__ hidden,
        const float* __restrict__ emb,
        const float* __restrict__ attn_W,
        const float* __restrict__ attn_b,
        const float* __restrict__ comb_W,
        const float* __restrict__ comb_b,
        const float* __restrict__ W_ih,
        const float* __restrict__ W_hh,
        const float* __restrict__ b_ih,
        const float* __restrict__ b_hh,
        const float* __restrict__ out_W,
        const float* __restrict__ out_b,
        float* __restrict__ out) {
    __shared__ float s_emb[H];
    __shared__ float s_h0[H];
    __shared__ float s_vec[H];
    __shared__ float s_attnw[L];
    __shared__ float red[1024], red2[1024];
    __shared__ float s_outb[ROWS_PB];
    __shared__ float s_logits[ROWS_PB];

    const int t = threadIdx.x, b = blockIdx.x;
    const int wid = t >> 5, lane = t & 31;
    const uint64_t POL_L = mkpol_last();
    const uint64_t POL_F = mkpol_first();

    const int r0 = b * ROWS_PB;
    const int r1 = (r0 + ROWS_PB < V) ? (r0 + ROWS_PB) : V;
    const int nrows = r1 - r0;

    // preload emb row + hidden + out_b slice into shared
    {
        const float* er = emb + (size_t)x[0] * H;
        s_emb[t] = ldg1_pol(er + t, POL_L);
        s_h0[t] = ldg1(hidden + t);
        if (t < nrows) s_outb[t] = ldg1(out_b + r0 + t);
        __syncthreads();
    }

    // ---- Phase A: attn-score quarter partials (2048 jobs)
    //      + W_hh gate GEMV (3072 jobs) — depend only on inputs --------------
    for (int job = b * NW + wid; job < 5120; job += GRID * NW) {
        if (job < 2048) {
            const int row = job >> 2, q = job & 3;
            const float* vp = (q < 2) ? (s_emb + q * 512) : (s_h0 + (q - 2) * 512);
            const float4* Wr = (const float4*)(attn_W + (size_t)row * (2 * H) + q * 512);
            const float4* sv = (const float4*)vp;
            float4 w[4];
#pragma unroll
            for (int i = 0; i < 4; i++) w[i] = ldg4_pol(Wr + lane + i * 32, POL_L);
            float acc = 0.f;
#pragma unroll
            for (int i = 0; i < 4; i++) {
                float4 v = sv[lane + i * 32];
                acc += w[i].x * v.x + w[i].y * v.y + w[i].z * v.z + w[i].w * v.w;
            }
            acc = wsum(acc);
            if (lane == 0) g_qpart[job] = acc;
        } else {
            const int r = job - 2048;
            const float4* Wr = (const float4*)(W_hh + (size_t)r * H);
            const float4* sv = (const float4*)s_h0;
            float4 w[8];
#pragma unroll
            for (int i = 0; i < 8; i++) w[i] = ldg4_pol(Wr + lane + i * 32, POL_L);
            float acc = 0.f;
#pragma unroll
            for (int i = 0; i < 8; i++) {
                float4 v = sv[lane + i * 32];
                acc += w[i].x * v.x + w[i].y * v.y + w[i].z * v.z + w[i].w * v.w;
            }
            acc = wsum(acc);
            if (lane == 0) g_gates[3 * H + r] = acc + ldg1(b_hh + r);
        }
    }
    gbar(0);

    // ---- Phase B: blocks 0..63: redundant softmax (L=512), then attn apply -
    if (b < 64) {
        float sc = NEG_SENT;
        if (t < L)
            sc = g_qpart[4 * t] + g_qpart[4 * t + 1] + g_qpart[4 * t + 2]
               + g_qpart[4 * t + 3] + ldg1(attn_b + t);
        red[t] = sc;
        __syncthreads();
        for (int o = 512; o; o >>= 1) {
            if (t < o) red[t] = fmaxf(red[t], red[t + o]);
            __syncthreads();
        }
        const float m = red[0];
        __syncthreads();
        const float e = (t < L) ? expf(sc - m) : 0.f;
        red[t] = e;
        __syncthreads();
        for (int o = 512; o; o >>= 1) {
            if (t < o) red[t] += red[t + o];
            __syncthreads();
        }
        if (t < L) {
            const float aw = e / red[0];
            s_attnw[t] = aw;
            if (b == 0) out[V + t] = aw;
        }
        __syncthreads();

        const int lc = b >> 3, jc = b & 7;
        const int j = jc * 128 + (t & 127);
        const int sub = t >> 7;                  // 0..7, 8 L-rows each
        const int l0 = lc * 64 + sub * 8;
        float ev[8];
#pragma unroll
        for (int u = 0; u < 8; u++) ev[u] = ldg1_pol(enc + (size_t)(l0 + u) * H + j, POL_L);
        float acc = 0.f;
#pragma unroll
        for (int u = 0; u < 8; u++) acc += s_attnw[l0 + u] * ev[u];
        red[t] = acc;
        __syncthreads();
        if (t < 512) red[t] += red[t + 512];
        __syncthreads();
        if (t < 256) red[t] += red[t + 256];
        __syncthreads();
        if (t < 128)
            g_attn_partial[lc][jc * 128 + t] = red[t] + red[t + 128];
    }
    gbar(1);

    // ---- Phase C: blocks 0..63: combine + relu (16 rows/block, 2 warps/row)
    if (b < 64) {
        {
            float a = 0.f;
#pragma unroll
            for (int c = 0; c < 8; c++) a += g_attn_partial[c][t];
            s_vec[t] = a;
        }
        __syncthreads();
        const int row = b * 16 + (wid >> 1), half = wid & 1;
        const float* vp = half ? s_vec : s_emb;
        const float4* Wr = (const float4*)(comb_W + (size_t)row * (2 * H) + half * H);
        const float4* sv = (const float4*)vp;
        float4 w[8];
#pragma unroll
        for (int i = 0; i < 8; i++) w[i] = ldg4_pol(Wr + lane + i * 32, POL_L);
        float acc = 0.f;
#pragma unroll
        for (int i = 0; i < 8; i++) {
            float4 v = sv[lane + i * 32];
            acc += w[i].x * v.x + w[i].y * v.y + w[i].z * v.z + w[i].w * v.w;
        }
        acc = wsum(acc);
        if (lane == 0) red[wid] = acc;
        __syncthreads();
        if (t < 16) {
            const int r = b * 16 + t;
            g_gru_in[r] = fmaxf(red[2 * t] + red[2 * t + 1] + ldg1(comb_b + r), 0.f);
        }
    }
    gbar(2);

    // ---- Phase D: W_ih gate GEMV (3072 warp-jobs) --------------------------
    s_vec[t] = g_gru_in[t];
    __syncthreads();
    for (int job = b * NW + wid; job < 3 * H; job += GRID * NW) {
        const float4* Wr = (const float4*)(W_ih + (size_t)job * H);
        const float4* sv = (const float4*)s_vec;
        float4 w[8];
#pragma unroll
        for (int i = 0; i < 8; i++) w[i] = ldg4_pol(Wr + lane + i * 32, POL_L);
        float acc = 0.f;
#pragma unroll
        for (int i = 0; i < 8; i++) {
            float4 v = sv[lane + i * 32];
            acc += w[i].x * v.x + w[i].y * v.y + w[i].z * v.z + w[i].w * v.w;
        }
        acc = wsum(acc);
        if (lane == 0) g_gates[job] = acc + ldg1(b_ih + job);
    }
    gbar(3);

    // ---- Phase E: redundant GRU elementwise -> s_vec = h_new ---------------
    __syncthreads();
    {
        const int i = t;
        const float gxr = g_gates[i],         ghr = g_gates[3 * H + i];
        const float gxz = g_gates[H + i],     ghz = g_gates[4 * H + i];
        const float gxn = g_gates[2 * H + i], ghn = g_gates[5 * H + i];
        const float r = 1.f / (1.f + expf(-(gxr + ghr)));
        const float z = 1.f / (1.f + expf(-(gxz + ghz)));
        const float n = tanhf(gxn + r * ghn);
        s_vec[i] = (1.f - z) * n + z * s_h0[i];
    }
    __syncthreads();

    // ---- Phase E2: big GEMV, warp-per-row; sticky prefix pinned in L2 ------
    for (int r = r0 + wid; r < r1; r += NW) {
        const float4* Wr = (const float4*)(out_W + (size_t)r * H);
        const float4* sv = (const float4*)s_vec;
        const uint64_t pol = (r - r0 < STICKY_ROWS) ? POL_L : POL_F;
        float4 w[8];
#pragma unroll
        for (int i = 0; i < 8; i++) w[i] = ldg4_pol(Wr + lane + i * 32, pol);
        float acc = 0.f;
#pragma unroll
        for (int i = 0; i < 8; i++) {
            float4 v = sv[lane + i * 32];
            acc += w[i].x * v.x + w[i].y * v.y + w[i].z * v.z + w[i].w * v.w;
        }
        acc = wsum(acc);
        if (lane == 0) s_logits[r - r0] = acc + s_outb[r - r0];
    }
    __syncthreads();

    // per-block LSE partial over own rows (smem-resident logits)
    {
        red[t]  = (t < nrows) ? s_logits[t] : NEG_SENT;
        red2[t] = (t < nrows) ? 1.f : 0.f;
        __syncthreads();
        for (int o = 512; o; o >>= 1) {
            if (t < o) {
                const float m2 = red[t + o], s2 = red2[t + o];
                const float nm = fmaxf(red[t], m2);
                red2[t] = red2[t] * expf(red[t] - nm) + s2 * expf(m2 - nm);
                red[t] = nm;
            }
            __syncthreads();
        }
        if (t == 0) { g_pm[b] = red[0]; g_ps[b] = red2[0]; }
    }
    gbar(4);

    // ---- Phase F: redundant combine of 148 partials (identical tree) -------
    {
        if (t < 256) {
            red[t]  = (t < GRID) ? g_pm[t] : NEG_SENT;
            red2[t] = (t < GRID) ? g_ps[t] : 0.f;
        }
        __syncthreads();
        for (int o = 128; o; o >>= 1) {
            if (t < o) {
                const float m2 = red[t + o], s2 = red2[t + o];
                const float nm = fmaxf(red[t], m2);
                red2[t] = red2[t] * expf(red[t] - nm) + s2 * expf(m2 - nm);
                red[t] = nm;
            }
            __syncthreads();
        }
        const float lse = red[0] + logf(red2[0]);
        if (t < nrows) out[r0 + t] = s_logits[t] - lse;
    }
}

extern "C" void kernel_launch(void* const* d_in, const int* in_sizes, int n_in,
                              void* d_out, int out_size) {
    const int*   x      = (const int*)  d_in[0];
    const float* enc    = (const float*)d_in[1];
    const float* hidden = (const float*)d_in[2];
    const float* emb    = (const float*)d_in[3];
    const float* attn_W = (const float*)d_in[4];
    const float* attn_b = (const float*)d_in[5];
    const float* comb_W = (const float*)d_in[6];
    const float* comb_b = (const float*)d_in[7];
    const float* W_ih   = (const float*)d_in[8];
    const float* W_hh   = (const float*)d_in[9];
    const float* b_ih   = (const float*)d_in[10];
    const float* b_hh   = (const float*)d_in[11];
    const float* out_W  = (const float*)d_in[12];
    const float* out_b  = (const float*)d_in[13];
    float* out = (float*)d_out;   // [0,V): logp ; [V,V+L): attn_weights

    k_reset<<<1, 32>>>();
    k_fused<<<GRID, TPB>>>(x, enc, hidden, emb, attn_W, attn_b, comb_W, comb_b,
                           W_ih, W_hh, b_ih, b_hh, out_W, out_b, out);
}